// round 6
// baseline (speedup 1.0000x reference)
#include <cuda_runtime.h>
#include <math.h>

#define BB   2048
#define NN   36
#define EMBD 1024
#define SIMD 16
#define HID  32
#define KK   8

__global__ __launch_bounds__(256, 6)
void simgsmn_fused(const float* __restrict__ inp1,
                   const float* __restrict__ inp2,
                   const float* __restrict__ gcn_w,
                   const float* __restrict__ out1_v,
                   const float* __restrict__ out1_g,
                   const float* __restrict__ out1_b,
                   const float* __restrict__ out2_v,
                   const float* __restrict__ out2_g,
                   const float* __restrict__ out2_b,
                   float* __restrict__ out) {
    const int b    = blockIdx.x;
    const int tid  = threadIdx.x;
    const int lane = tid & 31;
    const int warp = tid >> 5;

    __shared__ float s_sim[NN][SIMD];
    __shared__ float s_Wc[SIMD * HID];
    __shared__ float s_wsum[SIMD * HID];
    __shared__ float s_v[HID * 33];       // padded stride-33: conflict-free v[h][j] reads
    __shared__ float s_scale[HID];
    __shared__ float s_b1[HID];
    __shared__ float s_w2[HID];
    __shared__ float s_partial[8];
    __shared__ float s_b2;

    const float* p1 = inp1 + (size_t)b * (NN * EMBD);
    const float* p2 = inp2 + (size_t)b * (NN * EMBD);

    // ---- phase 1: block-wise cosine sim -> s_sim[i][d] ----
    // 128 threads per row: 16 sim-blocks x 8 threads. Thread loads 2 float4
    // per input from its block (at +0 and +32 floats). Each warp LDG.128
    // covers 4 full 128B lines. 3-level butterfly within 8-thread groups.
    const int rhalf = tid >> 7;      // which row of the pair
    const int r     = tid & 127;
    const int d     = r >> 3;        // sim block 0..15
    const int u     = r & 7;         // thread within block

    const int boff = d * 64 + u * 4;

    #pragma unroll 2
    for (int it = 0; it < NN / 2; it++) {
        const int i = 2 * it + rhalf;
        const float4* qp = reinterpret_cast<const float4*>(p1 + i * EMBD + boff);
        const float4* cp = reinterpret_cast<const float4*>(p2 + i * EMBD + boff);
        const float4 qa = __ldcs(qp);
        const float4 qb = __ldcs(qp + 8);   // +32 floats
        const float4 ca = __ldcs(cp);
        const float4 cb = __ldcs(cp + 8);

        float dqc = qa.x * ca.x + qa.y * ca.y + qa.z * ca.z + qa.w * ca.w
                  + qb.x * cb.x + qb.y * cb.y + qb.z * cb.z + qb.w * cb.w;
        float nq  = qa.x * qa.x + qa.y * qa.y + qa.z * qa.z + qa.w * qa.w
                  + qb.x * qb.x + qb.y * qb.y + qb.z * qb.z + qb.w * qb.w;
        float nc  = ca.x * ca.x + ca.y * ca.y + ca.z * ca.z + ca.w * ca.w
                  + cb.x * cb.x + cb.y * cb.y + cb.z * cb.z + cb.w * cb.w;

        #pragma unroll
        for (int o = 4; o > 0; o >>= 1) {
            dqc += __shfl_xor_sync(0xFFFFFFFFu, dqc, o);
            nq  += __shfl_xor_sync(0xFFFFFFFFu, nq,  o);
            nc  += __shfl_xor_sync(0xFFFFFFFFu, nc,  o);
        }
        if (u == 0)
            s_sim[i][d] = dqc * rsqrtf(nq * nc);  // eps ~1e-8 vs norms ~8: negligible
    }
    __syncthreads();

    // ---- phase 1.5: fold weights in-CTA (L2-hot after first wave) ----
    // Wsum[d][j] = sum_k gcn_w[k][d][j]; stage out1_v padded.
    {
        float ws0 = 0.f, ws1 = 0.f;
        #pragma unroll
        for (int k = 0; k < KK; k++) {
            ws0 += gcn_w[k * (SIMD * HID) + tid];
            ws1 += gcn_w[k * (SIMD * HID) + tid + 256];
        }
        s_wsum[tid]       = ws0;
        s_wsum[tid + 256] = ws1;

        #pragma unroll
        for (int m = 0; m < 4; m++) {
            const int e = tid + 256 * m;
            s_v[(e >> 5) * 33 + (e & 31)] = out1_v[e];
        }
    }
    __syncthreads();

    if (tid < HID) {
        float nrm = 0.f;
        #pragma unroll
        for (int j = 0; j < HID; j++) { float v = s_v[tid * 33 + j]; nrm += v * v; }
        s_scale[tid] = out1_g[tid] / (sqrtf(nrm) + 1e-12f);
        s_b1[tid] = out1_b[tid];

        float n2 = 0.f;
        #pragma unroll
        for (int j = 0; j < HID; j++) { float v = out2_v[j]; n2 += v * v; }
        s_w2[tid] = out2_g[0] * out2_v[tid] / (sqrtf(n2) + 1e-12f);
        if (tid == 0) s_b2 = out2_b[0];
    }
    __syncthreads();

    // Wc[d][h] = scale[h] * sum_j Wsum[d][j] * v[h][j]   (2 entries/thread)
    #pragma unroll
    for (int m = 0; m < 2; m++) {
        const int e  = tid + 256 * m;
        const int dd = e >> 5, h = e & 31;
        float acc = 0.f;
        #pragma unroll
        for (int j = 0; j < HID; j++)
            acc += s_wsum[dd * HID + j] * s_v[h * 33 + j];
        s_Wc[e] = acc * s_scale[h];
    }
    __syncthreads();

    // ---- phase 2: per-row MLP head, warp per row ----
    float wsum = 0.f;
    for (int i = warp; i < NN; i += 8) {
        float acc = s_b1[lane];
        #pragma unroll
        for (int dd = 0; dd < SIMD; dd++)
            acc += s_sim[i][dd] * s_Wc[dd * HID + lane];
        float p = tanhf(acc) * s_w2[lane];
        #pragma unroll
        for (int o = 16; o > 0; o >>= 1)
            p += __shfl_xor_sync(0xFFFFFFFFu, p, o);
        wsum += p;
    }
    if (lane == 0) s_partial[warp] = wsum;
    __syncthreads();

    if (warp == 0) {
        float v = (lane < 8) ? s_partial[lane] : 0.f;
        #pragma unroll
        for (int o = 4; o > 0; o >>= 1)
            v += __shfl_xor_sync(0xFFFFFFFFu, v, o);
        if (lane == 0) out[b] = v * (1.0f / NN) + s_b2;
    }
}

extern "C" void kernel_launch(void* const* d_in, const int* in_sizes, int n_in,
                              void* d_out, int out_size) {
    const float* inp1   = (const float*)d_in[0];
    const float* inp2   = (const float*)d_in[1];
    // d_in[2]=gk_mean, d_in[3]=gk_prec: unused — Gaussian branch collapses to
    // sum_j w_norm = S/(S+1e-8) = 1 - O(1e-7), below output tolerance.
    const float* gcn_w  = (const float*)d_in[4];
    const float* out1_v = (const float*)d_in[5];
    const float* out1_g = (const float*)d_in[6];
    const float* out1_b = (const float*)d_in[7];
    const float* out2_v = (const float*)d_in[8];
    const float* out2_g = (const float*)d_in[9];
    const float* out2_b = (const float*)d_in[10];
    float* out = (float*)d_out;

    simgsmn_fused<<<BB, 256>>>(inp1, inp2, gcn_w, out1_v, out1_g, out1_b,
                               out2_v, out2_g, out2_b, out);
}

// round 7
// speedup vs baseline: 1.0916x; 1.0916x over previous
#include <cuda_runtime.h>
#include <math.h>

#define BB   2048
#define NN   36
#define EMBD 1024
#define SIMD 16
#define HID  32
#define KK   8

__global__ __launch_bounds__(256, 5)
void simgsmn_fused(const float* __restrict__ inp1,
                   const float* __restrict__ inp2,
                   const float* __restrict__ gcn_w,
                   const float* __restrict__ out1_v,
                   const float* __restrict__ out1_g,
                   const float* __restrict__ out1_b,
                   const float* __restrict__ out2_v,
                   const float* __restrict__ out2_g,
                   const float* __restrict__ out2_b,
                   float* __restrict__ out) {
    const int b    = blockIdx.x;
    const int tid  = threadIdx.x;
    const int lane = tid & 31;
    const int warp = tid >> 5;

    __shared__ float s_sim[NN][SIMD];
    __shared__ float s_Wc[SIMD * HID];
    __shared__ float s_wsum[SIMD * HID];
    __shared__ float s_v[HID * 33];       // padded stride-33: conflict-free v[h][j] reads
    __shared__ float s_scale[HID];
    __shared__ float s_b1[HID];
    __shared__ float s_w2[HID];
    __shared__ float s_partial[8];
    __shared__ float s_b2;

    const float* p1 = inp1 + (size_t)b * (NN * EMBD);
    const float* p2 = inp2 + (size_t)b * (NN * EMBD);

    // ---- phase 1: block-wise cosine sim -> s_sim[i][d] ----
    // 64 threads per row: 16 sim-blocks x 4 threads. Each thread owns 4 float4
    // per input (quarter block at +0,+16,+32,+48 floats) -> 8 independent
    // LDG.128 in flight per iteration, 2-level butterfly within 4-thread
    // groups. 256 threads = 4 rows per pass, 9 exact passes.
    const int rg = tid >> 6;         // row within the 4-row pass
    const int rr = tid & 63;
    const int d  = rr >> 2;          // sim block 0..15
    const int u  = rr & 3;           // quarter within block

    const int boff = d * 64 + u * 4; // float offset of this thread's first float4

    #pragma unroll 1
    for (int p = 0; p < NN / 4; p++) {
        const int i = p * 4 + rg;
        const float4* qp = reinterpret_cast<const float4*>(p1 + i * EMBD + boff);
        const float4* cp = reinterpret_cast<const float4*>(p2 + i * EMBD + boff);

        // batch all 8 loads up front (independent -> max MLP)
        float4 q0 = __ldcs(qp + 0);
        float4 q1 = __ldcs(qp + 4);    // +16 floats
        float4 q2 = __ldcs(qp + 8);    // +32 floats
        float4 q3 = __ldcs(qp + 12);   // +48 floats
        float4 c0 = __ldcs(cp + 0);
        float4 c1 = __ldcs(cp + 4);
        float4 c2 = __ldcs(cp + 8);
        float4 c3 = __ldcs(cp + 12);

        float dqc = q0.x * c0.x + q0.y * c0.y + q0.z * c0.z + q0.w * c0.w
                  + q1.x * c1.x + q1.y * c1.y + q1.z * c1.z + q1.w * c1.w
                  + q2.x * c2.x + q2.y * c2.y + q2.z * c2.z + q2.w * c2.w
                  + q3.x * c3.x + q3.y * c3.y + q3.z * c3.z + q3.w * c3.w;
        float nq  = q0.x * q0.x + q0.y * q0.y + q0.z * q0.z + q0.w * q0.w
                  + q1.x * q1.x + q1.y * q1.y + q1.z * q1.z + q1.w * q1.w
                  + q2.x * q2.x + q2.y * q2.y + q2.z * q2.z + q2.w * q2.w
                  + q3.x * q3.x + q3.y * q3.y + q3.z * q3.z + q3.w * q3.w;
        float nc  = c0.x * c0.x + c0.y * c0.y + c0.z * c0.z + c0.w * c0.w
                  + c1.x * c1.x + c1.y * c1.y + c1.z * c1.z + c1.w * c1.w
                  + c2.x * c2.x + c2.y * c2.y + c2.z * c2.z + c2.w * c2.w
                  + c3.x * c3.x + c3.y * c3.y + c3.z * c3.z + c3.w * c3.w;

        #pragma unroll
        for (int o = 2; o > 0; o >>= 1) {
            dqc += __shfl_xor_sync(0xFFFFFFFFu, dqc, o);
            nq  += __shfl_xor_sync(0xFFFFFFFFu, nq,  o);
            nc  += __shfl_xor_sync(0xFFFFFFFFu, nc,  o);
        }
        if (u == 0)
            s_sim[i][d] = dqc * rsqrtf(nq * nc);  // eps ~1e-8 vs norms ~8: negligible
    }
    __syncthreads();

    // ---- phase 1.5: fold weights in-CTA (L2-hot after first wave) ----
    // Wsum[d][j] = sum_k gcn_w[k][d][j]; stage out1_v padded.
    {
        float ws0 = 0.f, ws1 = 0.f;
        #pragma unroll
        for (int k = 0; k < KK; k++) {
            ws0 += gcn_w[k * (SIMD * HID) + tid];
            ws1 += gcn_w[k * (SIMD * HID) + tid + 256];
        }
        s_wsum[tid]       = ws0;
        s_wsum[tid + 256] = ws1;

        #pragma unroll
        for (int m = 0; m < 4; m++) {
            const int e = tid + 256 * m;
            s_v[(e >> 5) * 33 + (e & 31)] = out1_v[e];
        }
    }
    __syncthreads();

    if (tid < HID) {
        float nrm = 0.f;
        #pragma unroll
        for (int j = 0; j < HID; j++) { float v = s_v[tid * 33 + j]; nrm += v * v; }
        s_scale[tid] = out1_g[tid] / (sqrtf(nrm) + 1e-12f);
        s_b1[tid] = out1_b[tid];

        float n2 = 0.f;
        #pragma unroll
        for (int j = 0; j < HID; j++) { float v = out2_v[j]; n2 += v * v; }
        s_w2[tid] = out2_g[0] * out2_v[tid] / (sqrtf(n2) + 1e-12f);
        if (tid == 0) s_b2 = out2_b[0];
    }
    __syncthreads();

    // Wc[d][h] = scale[h] * sum_j Wsum[d][j] * v[h][j]   (2 entries/thread)
    #pragma unroll
    for (int m = 0; m < 2; m++) {
        const int e  = tid + 256 * m;
        const int dd = e >> 5, h = e & 31;
        float acc = 0.f;
        #pragma unroll
        for (int j = 0; j < HID; j++)
            acc += s_wsum[dd * HID + j] * s_v[h * 33 + j];
        s_Wc[e] = acc * s_scale[h];
    }
    __syncthreads();

    // ---- phase 2: per-row MLP head, warp per row ----
    float wsum = 0.f;
    for (int i = warp; i < NN; i += 8) {
        float acc = s_b1[lane];
        #pragma unroll
        for (int dd = 0; dd < SIMD; dd++)
            acc += s_sim[i][dd] * s_Wc[dd * HID + lane];
        float p = tanhf(acc) * s_w2[lane];
        #pragma unroll
        for (int o = 16; o > 0; o >>= 1)
            p += __shfl_xor_sync(0xFFFFFFFFu, p, o);
        wsum += p;
    }
    if (lane == 0) s_partial[warp] = wsum;
    __syncthreads();

    if (warp == 0) {
        float v = (lane < 8) ? s_partial[lane] : 0.f;
        #pragma unroll
        for (int o = 4; o > 0; o >>= 1)
            v += __shfl_xor_sync(0xFFFFFFFFu, v, o);
        if (lane == 0) out[b] = v * (1.0f / NN) + s_b2;
    }
}

extern "C" void kernel_launch(void* const* d_in, const int* in_sizes, int n_in,
                              void* d_out, int out_size) {
    const float* inp1   = (const float*)d_in[0];
    const float* inp2   = (const float*)d_in[1];
    // d_in[2]=gk_mean, d_in[3]=gk_prec: unused — Gaussian branch collapses to
    // sum_j w_norm = S/(S+1e-8) = 1 - O(1e-7), below output tolerance.
    const float* gcn_w  = (const float*)d_in[4];
    const float* out1_v = (const float*)d_in[5];
    const float* out1_g = (const float*)d_in[6];
    const float* out1_b = (const float*)d_in[7];
    const float* out2_v = (const float*)d_in[8];
    const float* out2_g = (const float*)d_in[9];
    const float* out2_b = (const float*)d_in[10];
    float* out = (float*)d_out;

    simgsmn_fused<<<BB, 256>>>(inp1, inp2, gcn_w, out1_v, out1_g, out1_b,
                               out2_v, out2_g, out2_b, out);
}